// round 16
// baseline (speedup 1.0000x reference)
#include <cuda_runtime.h>
#include <cuda_fp16.h>
#include <cstdint>

// Problem constants
#define BB 2
#define PP 64
#define NN 256
#define CC 512
#define HH 8
#define DD 64
#define BP (BB*PP)        // 128
#define MROWS (BP*NN)     // 32768
#define INV_TEMP 0.125f
#define LN_EPS 1e-5f

// ---------------- scratch (static device globals; allocation-free) ----------------
__device__ __half g_a[3][(size_t)MROWS * CC];   // LN'd q/k/v (A of proj GEMMs)
__device__ __half g_w[4][(size_t)CC * CC];      // Wq,Wk,Wv,Wo
__device__ __half g_p[3][(size_t)MROWS * CC];   // projected q/k/v
__device__ __half g_ao[(size_t)MROWS * CC];     // attention output (A of out GEMM)

// ---------------- helpers ----------------
__device__ __forceinline__ uint32_t s2u(const void* p) {
    uint32_t a;
    asm("{ .reg .u64 t; cvta.to.shared.u64 t, %1; cvt.u32.u64 %0, t; }" : "=r"(a) : "l"(p));
    return a;
}

__device__ __forceinline__ void cp16(uint32_t dst, const void* src) {
    asm volatile("cp.async.cg.shared.global [%0], [%1], 16;" :: "r"(dst), "l"(src) : "memory");
}

__device__ __forceinline__ void ldm4(uint32_t* r, uint32_t addr) {
    asm volatile("ldmatrix.sync.aligned.m8n8.x4.shared.b16 {%0,%1,%2,%3}, [%4];"
                 : "=r"(r[0]), "=r"(r[1]), "=r"(r[2]), "=r"(r[3]) : "r"(addr));
}

__device__ __forceinline__ void ldm4t(uint32_t* r, uint32_t addr) {
    asm volatile("ldmatrix.sync.aligned.m8n8.x4.trans.shared.b16 {%0,%1,%2,%3}, [%4];"
                 : "=r"(r[0]), "=r"(r[1]), "=r"(r[2]), "=r"(r[3]) : "r"(addr));
}

__device__ __forceinline__ void mma16816(float* c, const uint32_t* a, const uint32_t* b) {
    asm volatile(
        "mma.sync.aligned.m16n8k16.row.col.f32.f16.f16.f32 "
        "{%0,%1,%2,%3}, {%4,%5,%6,%7}, {%8,%9}, {%0,%1,%2,%3};"
        : "+f"(c[0]), "+f"(c[1]), "+f"(c[2]), "+f"(c[3])
        : "r"(a[0]), "r"(a[1]), "r"(a[2]), "r"(a[3]), "r"(b[0]), "r"(b[1]));
}

__device__ __forceinline__ uint32_t packh2(float a, float b) {
    __half2 h = __floats2half2_rn(a, b);
    return *reinterpret_cast<uint32_t*>(&h);
}

// ---------------- kernel 1: fused LayerNorm + fp16 convert, warp-per-row ----------------
__global__ __launch_bounds__(256) void split_ln_kernel(
    const float* __restrict__ q, const float* __restrict__ k, const float* __restrict__ v,
    const float* __restrict__ gq, const float* __restrict__ bq,
    const float* __restrict__ gk, const float* __restrict__ bk,
    const float* __restrict__ gv, const float* __restrict__ bv)
{
    const int lane = threadIdx.x & 31;
    const int row = blockIdx.x * 8 + (threadIdx.x >> 5);
    const int t = (row >= 2 * MROWS) ? 2 : (row >= MROWS ? 1 : 0);
    const int r = row - t * MROWS;
    const float* X = (t == 0 ? q : (t == 1 ? k : v)) + (size_t)r * CC;
    const float* G = (t == 0 ? gq : (t == 1 ? gk : gv));
    const float* Bb = (t == 0 ? bq : (t == 1 ? bk : bv));
    __half* H = g_a[t] + (size_t)r * CC;

    float4 u[4];
    float s = 0.f, ss = 0.f;
#pragma unroll
    for (int i = 0; i < 4; i++) {
        u[i] = reinterpret_cast<const float4*>(X)[lane + 32 * i];
        s  += u[i].x + u[i].y + u[i].z + u[i].w;
        ss += u[i].x * u[i].x + u[i].y * u[i].y + u[i].z * u[i].z + u[i].w * u[i].w;
    }
#pragma unroll
    for (int o = 16; o; o >>= 1) {
        s  += __shfl_xor_sync(0xffffffffu, s, o);
        ss += __shfl_xor_sync(0xffffffffu, ss, o);
    }
    float mu = s * (1.f / CC);
    float rs = rsqrtf(ss * (1.f / CC) - mu * mu + LN_EPS);

#pragma unroll
    for (int i = 0; i < 4; i++) {
        int j = lane + 32 * i;
        float4 g4 = reinterpret_cast<const float4*>(G)[j];
        float4 b4 = reinterpret_cast<const float4*>(Bb)[j];
        float y0 = (u[i].x - mu) * rs * g4.x + b4.x;
        float y1 = (u[i].y - mu) * rs * g4.y + b4.y;
        float y2 = (u[i].z - mu) * rs * g4.z + b4.z;
        float y3 = (u[i].w - mu) * rs * g4.w + b4.w;
        reinterpret_cast<uint2*>(H)[j] = make_uint2(packh2(y0, y1), packh2(y2, y3));
    }
}

// ---------------- kernel 2: weight fp32 -> fp16 (all 4 in one launch) ----------------
__global__ __launch_bounds__(256) void split_w_kernel(
    const float* __restrict__ w0, const float* __restrict__ w1,
    const float* __restrict__ w2, const float* __restrict__ w3)
{
    const int mode = blockIdx.y;
    const float* src = (mode == 0 ? w0 : (mode == 1 ? w1 : (mode == 2 ? w2 : w3)));
    __half* H = g_w[mode];
    int i = blockIdx.x * 256 + threadIdx.x;
    float4 u = reinterpret_cast<const float4*>(src)[i];
    reinterpret_cast<uint2*>(H)[i] = make_uint2(packh2(u.x, u.y), packh2(u.z, u.w));
}

// ---------------- kernel 3: HMMA fp16 GEMM (BK=64 stages, 3-stage, 1 barrier/iter) ----------------
// A/B stage tiles 128x64 fp16 = 128B rows (8 chunks), swizzle chunk^(row&7).
#define TILE_B 16384
#define STAGE_B 32768
#define GSMEM (3 * STAGE_B)
#define NKI (CC / 64)

__global__ __launch_bounds__(256, 2)
void mma_gemm_kernel(int base_mode, float* __restrict__ out_param, const float* __restrict__ bias_param)
{
    extern __shared__ char smc[];
    const uint32_t sb = s2u(smc);
    const int tid = threadIdx.x, wid = tid >> 5, lane = tid & 31;
    const int warp_m = wid >> 2, warp_n = wid & 3;       // 2 x 4 warps
    const int m0 = blockIdx.y * 128, n0 = blockIdx.x * 128;
    const int mode = base_mode + blockIdx.z;

    const __half* A = (mode < 3) ? g_a[mode] : g_ao;
    const __half* B = g_w[mode];

    float acc[4][4][4];
#pragma unroll
    for (int i = 0; i < 4; i++)
#pragma unroll
        for (int j = 0; j < 4; j++)
#pragma unroll
            for (int x = 0; x < 4; x++) acc[i][j][x] = 0.f;

    const int lrow = tid >> 1;          // 0..127
    const int lc0  = (tid & 1) * 4;     // chunk 0 or 4

    auto issue_loads = [&](int s, int k0) {
        uint32_t sst = sb + s * STAGE_B;
        const size_t ga = (size_t)(m0 + lrow) * CC + k0;
        const size_t gb = (size_t)(n0 + lrow) * CC + k0;
#pragma unroll
        for (int i = 0; i < 4; i++) {
            int c = lc0 + i;
            uint32_t d = (uint32_t)(lrow * 128 + ((c ^ (lrow & 7)) << 4));
            cp16(sst + 0 * TILE_B + d, A + ga + c * 8);
            cp16(sst + 1 * TILE_B + d, B + gb + c * 8);
        }
    };

    issue_loads(0, 0);
    asm volatile("cp.async.commit_group;" ::: "memory");
    issue_loads(1, 64);
    asm volatile("cp.async.commit_group;" ::: "memory");

    for (int it = 0; it < NKI; it++) {
        asm volatile("cp.async.wait_group 1;" ::: "memory");
        __syncthreads();   // all warps done reading the buffer we are about to refill

        if (it + 2 < NKI) issue_loads((it + 2) % 3, (it + 2) * 64);
        asm volatile("cp.async.commit_group;" ::: "memory");

        const uint32_t st = sb + (it % 3) * STAGE_B;
#pragma unroll
        for (int kk = 0; kk < 4; kk++) {
            uint32_t af[4][4], bf[2][4];
            int ar = warp_m * 64 + (lane & 7) + ((lane >> 3) & 1) * 8;
            int ac = kk * 2 + ((lane >> 4) & 1);
            int br = warp_n * 32 + (lane & 7) + ((lane >> 4) & 1) * 8;
            int bc = kk * 2 + ((lane >> 3) & 1);

#pragma unroll
            for (int np = 0; np < 2; np++) {
                int r = br + np * 16;
                ldm4(bf[np], st + 1 * TILE_B + r * 128 + (((bc ^ (r & 7)) & 7) << 4));
            }
#pragma unroll
            for (int mt = 0; mt < 4; mt++) {
                int r = ar + mt * 16;
                ldm4(af[mt], st + 0 * TILE_B + r * 128 + (((ac ^ (r & 7)) & 7) << 4));
            }
#pragma unroll
            for (int mt = 0; mt < 4; mt++)
#pragma unroll
                for (int nt = 0; nt < 4; nt++)
                    mma16816(acc[mt][nt], af[mt], &bf[nt >> 1][(nt & 1) * 2]);
        }
    }

    if (mode < 3) {
        __half* H = g_p[mode];
#pragma unroll
        for (int mt = 0; mt < 4; mt++) {
#pragma unroll
            for (int nt = 0; nt < 4; nt++) {
                int r = m0 + warp_m * 64 + mt * 16 + (lane >> 2);
                int col = n0 + warp_n * 32 + nt * 8 + (lane & 3) * 2;
                *reinterpret_cast<uint32_t*>(H + (size_t)r * CC + col) =
                    packh2(acc[mt][nt][0], acc[mt][nt][1]);
                *reinterpret_cast<uint32_t*>(H + (size_t)(r + 8) * CC + col) =
                    packh2(acc[mt][nt][2], acc[mt][nt][3]);
            }
        }
    } else {
        float* O = out_param;
        const float* bias = bias_param;
#pragma unroll
        for (int mt = 0; mt < 4; mt++) {
#pragma unroll
            for (int nt = 0; nt < 4; nt++) {
                int r = m0 + warp_m * 64 + mt * 16 + (lane >> 2);
                int col = n0 + warp_n * 32 + nt * 8 + (lane & 3) * 2;
                float b0 = bias[col], b1 = bias[col + 1];
                float2 v0 = {acc[mt][nt][0] + b0, acc[mt][nt][1] + b1};
                float2 v1 = {acc[mt][nt][2] + b0, acc[mt][nt][3] + b1};
                *reinterpret_cast<float2*>(O + (size_t)r * CC + col) = v0;
                *reinterpret_cast<float2*>(O + (size_t)(r + 8) * CC + col) = v1;
            }
        }
    }
}

// ---------------- kernel 4: fp16 attention, 512 thr / 16 warps, no-max softmax ----------------
#define AK 0
#define AV 32768
#define AQ 65536
#define STT 73728
#define AOPH 75776
#define ASMEM (AOPH + 32768)   // 108544

// fp16 partial-O word address: buffer wb, row wr (0..63), logical col-word lw (0..31)
__device__ __forceinline__ uint32_t opw(int wb, int wr, int lw) {
    return (uint32_t)(AOPH + wb * 8192 + wr * 128 + ((lw ^ ((wr & 7) << 2)) << 2));
}

__global__ __launch_bounds__(512, 1) void attn_tc_kernel(
    const float* __restrict__ mask, const float* __restrict__ pos)
{
    extern __shared__ char smc[];
    const uint32_t sb = s2u(smc);
    const int h = blockIdx.x, bp = blockIdx.y;
    const int tid = threadIdx.x, wid = tid >> 5, lane = tid & 31;
    const int warp_m = wid >> 2, warp_n = wid & 3;    // 4 x 4 warps
    const int g = lane >> 2, tg = lane & 3;

    // K/V tiles: 256 rows x 64 fp16 = 128B rows, SW swizzle on 8 chunks
    for (int i = tid; i < 2048; i += 512) {
        int row = i >> 3, c = i & 7;
        uint32_t d = (uint32_t)(row * 128 + ((c ^ (row & 7)) << 4));
        size_t gg = (size_t)(bp * NN + row) * CC + h * DD + c * 8;
        cp16(sb + AK + d, g_p[1] + gg);
        cp16(sb + AV + d, g_p[2] + gg);
    }
    asm volatile("cp.async.commit_group;" ::: "memory");

    const size_t mbase = (size_t)bp * NN * NN;
    const size_t pbase = (size_t)h * NN * NN;

    for (int it = 0; it < 4; it++) {
        // Q tile (64 rows x 8 chunks = 512), one chunk per thread
        {
            int row = tid >> 3, c = tid & 7;
            uint32_t d = (uint32_t)(row * 128 + ((c ^ (row & 7)) << 4));
            size_t gg = (size_t)(bp * NN + it * 64 + row) * CC + h * DD + c * 8;
            cp16(sb + AQ + d, g_p[0] + gg);
        }
        asm volatile("cp.async.commit_group;" ::: "memory");
        asm volatile("cp.async.wait_group 0;" ::: "memory");
        __syncthreads();

        // ---- S = Q K^T (warp: 16 rows x 64 cols, k=64), kept in regs ----
        float cS[8][4];
#pragma unroll
        for (int i = 0; i < 8; i++)
#pragma unroll
            for (int x = 0; x < 4; x++) cS[i][x] = 0.f;

#pragma unroll
        for (int ks = 0; ks < 4; ks++) {
            uint32_t ah[4];
            {
                int ar = warp_m * 16 + (lane & 7) + ((lane >> 3) & 1) * 8;
                int ac = ks * 2 + ((lane >> 4) & 1);
                ldm4(ah, sb + AQ + ar * 128 + (((ac ^ (ar & 7)) & 7) << 4));
            }
#pragma unroll
            for (int nt2 = 0; nt2 < 4; nt2++) {
                int br = warp_n * 64 + nt2 * 16 + (lane & 7) + ((lane >> 4) & 1) * 8;
                int bc = ks * 2 + ((lane >> 3) & 1);
                uint32_t bh[4];
                ldm4(bh, sb + AK + br * 128 + (((bc ^ (br & 7)) & 7) << 4));
                mma16816(cS[2 * nt2],     ah, bh);
                mma16816(cS[2 * nt2 + 1], ah, bh + 2);
            }
        }

        // ---- e = exp(mask*(s*INV_TEMP + pos)) in regs (no max subtraction) ----
        float s0 = 0.f, s1 = 0.f;
        {
            const int i0 = warp_m * 16 + g;
            const size_t mr0 = mbase + (size_t)(it * 64 + i0) * NN;
            const size_t pr0 = pbase + (size_t)(it * 64 + i0) * NN;
#pragma unroll
            for (int nt = 0; nt < 8; nt++) {
                int j = warp_n * 64 + nt * 8 + 2 * tg;
                float2 m0 = __ldg(reinterpret_cast<const float2*>(mask + mr0 + j));
                float2 p0 = __ldg(reinterpret_cast<const float2*>(pos  + pr0 + j));
                float2 m1 = __ldg(reinterpret_cast<const float2*>(mask + mr0 + 8 * NN + j));
                float2 p1 = __ldg(reinterpret_cast<const float2*>(pos  + pr0 + 8 * NN + j));
                cS[nt][0] = __expf(m0.x * (cS[nt][0] * INV_TEMP + p0.x));
                cS[nt][1] = __expf(m0.y * (cS[nt][1] * INV_TEMP + p0.y));
                cS[nt][2] = __expf(m1.x * (cS[nt][2] * INV_TEMP + p1.x));
                cS[nt][3] = __expf(m1.y * (cS[nt][3] * INV_TEMP + p1.y));
                s0 += cS[nt][0] + cS[nt][1];
                s1 += cS[nt][2] + cS[nt][3];
            }
        }
#pragma unroll
        for (int o = 1; o <= 2; o <<= 1) {
            s0 += __shfl_xor_sync(0xffffffffu, s0, o);
            s1 += __shfl_xor_sync(0xffffffffu, s1, o);
        }
        if (tg == 0) {
            int r0 = warp_m * 16 + g;
            *reinterpret_cast<float*>(smc + STT + (r0 * 4 + warp_n) * 4)       = s0;
            *reinterpret_cast<float*>(smc + STT + ((r0 + 8) * 4 + warp_n) * 4) = s1;
        }
        __syncthreads();

        // ---- global scale per row: 1 / total ----
        float sc0, sc1;
        {
            int r0 = warp_m * 16 + g;
            float4 a0 = *reinterpret_cast<float4*>(smc + STT + r0 * 16);
            sc0 = 1.f / (a0.x + a0.y + a0.z + a0.w);
            float4 b0 = *reinterpret_cast<float4*>(smc + STT + (r0 + 8) * 16);
            sc1 = 1.f / (b0.x + b0.y + b0.z + b0.w);
        }

        // ---- build P A-fragments from registers (FA2 C->A identity) ----
        uint32_t af[4][4];
#pragma unroll
        for (int kk = 0; kk < 4; kk++) {
            af[kk][0] = packh2(cS[2 * kk][0] * sc0,     cS[2 * kk][1] * sc0);
            af[kk][1] = packh2(cS[2 * kk][2] * sc1,     cS[2 * kk][3] * sc1);
            af[kk][2] = packh2(cS[2 * kk + 1][0] * sc0, cS[2 * kk + 1][1] * sc0);
            af[kk][3] = packh2(cS[2 * kk + 1][2] * sc1, cS[2 * kk + 1][3] * sc1);
        }

        // ---- partial O = P_slice @ V_slice (warp: 16 rows x 64 d-cols, k=64) ----
        float o[8][4];
#pragma unroll
        for (int i = 0; i < 8; i++)
#pragma unroll
            for (int x = 0; x < 4; x++) o[i][x] = 0.f;

#pragma unroll
        for (int ks = 0; ks < 4; ks++) {
#pragma unroll
            for (int nt16 = 0; nt16 < 4; nt16++) {
                int vr = warp_n * 64 + ks * 16 + (lane & 7) + ((lane >> 3) & 1) * 8;
                int vc = nt16 * 2 + ((lane >> 4) & 1);
                uint32_t bh[4];
                ldm4t(bh, sb + AV + vr * 128 + (((vc ^ (vr & 7)) & 7) << 4));
                mma16816(o[nt16 * 2],     af[ks], bh);
                mma16816(o[nt16 * 2 + 1], af[ks], bh + 2);
            }
        }

        // ---- write partial O (packed fp16) to this warp's buffer ----
        {
            int wr = warp_m * 16 + g;
#pragma unroll
            for (int nt = 0; nt < 8; nt++) {
                int lw = nt * 4 + tg;
                *reinterpret_cast<uint32_t*>(smc + opw(warp_n, wr, lw))     = packh2(o[nt][0], o[nt][1]);
                *reinterpret_cast<uint32_t*>(smc + opw(warp_n, wr + 8, lw)) = packh2(o[nt][2], o[nt][3]);
            }
        }
        __syncthreads();

        // ---- final: sum 4 fp16 partials, write fp16 g_ao ----
        {
            int ro = tid >> 3, jg = tid & 7;
            uint32_t base = (uint32_t)(AOPH + ro * 128 + ((uint32_t)(jg ^ (ro & 7)) << 4));
            float acc8[8];
#pragma unroll
            for (int x = 0; x < 8; x++) acc8[x] = 0.f;
#pragma unroll
            for (int w = 0; w < 4; w++) {
                uint4 u = *reinterpret_cast<uint4*>(smc + base + w * 8192);
                __half2 h0 = *reinterpret_cast<__half2*>(&u.x);
                __half2 h1 = *reinterpret_cast<__half2*>(&u.y);
                __half2 h2 = *reinterpret_cast<__half2*>(&u.z);
                __half2 h3 = *reinterpret_cast<__half2*>(&u.w);
                acc8[0] += __low2float(h0); acc8[1] += __high2float(h0);
                acc8[2] += __low2float(h1); acc8[3] += __high2float(h1);
                acc8[4] += __low2float(h2); acc8[5] += __high2float(h2);
                acc8[6] += __low2float(h3); acc8[7] += __high2float(h3);
            }
            uint4 wv;
            wv.x = packh2(acc8[0], acc8[1]);
            wv.y = packh2(acc8[2], acc8[3]);
            wv.z = packh2(acc8[4], acc8[5]);
            wv.w = packh2(acc8[6], acc8[7]);
            size_t gg = (size_t)(bp * NN + it * 64 + ro) * CC + h * DD + jg * 8;
            *reinterpret_cast<uint4*>(g_ao + gg) = wv;
        }
        // no barrier needed: next iter's smem writes are all behind its own barriers
    }
}

// ---------------- launch ----------------
extern "C" void kernel_launch(void* const* d_in, const int* in_sizes, int n_in,
                              void* d_out, int out_size)
{
    const float* q    = (const float*)d_in[0];
    const float* k    = (const float*)d_in[1];
    const float* v    = (const float*)d_in[2];
    const float* mask = (const float*)d_in[3];
    const float* pos  = (const float*)d_in[4];
    const float* gq   = (const float*)d_in[5];
    const float* bq   = (const float*)d_in[6];
    const float* gk   = (const float*)d_in[7];
    const float* bk   = (const float*)d_in[8];
    const float* gv   = (const float*)d_in[9];
    const float* bv   = (const float*)d_in[10];
    const float* Wq   = (const float*)d_in[11];
    const float* Wk   = (const float*)d_in[12];
    const float* Wv   = (const float*)d_in[13];
    const float* Wo   = (const float*)d_in[14];
    const float* bo   = (const float*)d_in[15];
    float* out = (float*)d_out;

    static bool attr_done = false;
    if (!attr_done) {
        cudaFuncSetAttribute(attn_tc_kernel, cudaFuncAttributeMaxDynamicSharedMemorySize, ASMEM);
        cudaFuncSetAttribute(mma_gemm_kernel, cudaFuncAttributeMaxDynamicSharedMemorySize, GSMEM);
        attr_done = true;
    }

    // 1. LN + fp16 convert of q,k,v (warp per row)
    split_ln_kernel<<<3 * MROWS / 8, 256>>>(q, k, v, gq, bq, gk, bk, gv, bv);

    // 2. weights -> fp16 (one launch, 4 modes)
    split_w_kernel<<<dim3(CC * CC / 4 / 256, 4), 256>>>(Wq, Wk, Wv, Wo);

    // 3. projection GEMMs (modes 0..2 via blockIdx.z)
    dim3 gp(CC / 128, MROWS / 128, 3);
    mma_gemm_kernel<<<gp, 256, GSMEM>>>(0, nullptr, nullptr);

    // 4. fp16 attention, register-resident P, no-max softmax
    attn_tc_kernel<<<dim3(HH, BP), 512, ASMEM>>>(mask, pos);

    // 5. output GEMM + bias
    dim3 go(CC / 128, MROWS / 128, 1);
    mma_gemm_kernel<<<go, 256, GSMEM>>>(3, out, bo);
}

// round 17
// speedup vs baseline: 1.0723x; 1.0723x over previous
#include <cuda_runtime.h>
#include <cuda_fp16.h>
#include <cstdint>

// Problem constants
#define BB 2
#define PP 64
#define NN 256
#define CC 512
#define HH 8
#define DD 64
#define BP (BB*PP)        // 128
#define MROWS (BP*NN)     // 32768
#define INV_TEMP 0.125f
#define LN_EPS 1e-5f

// ---------------- scratch (static device globals; allocation-free) ----------------
__device__ __half g_a[3][(size_t)MROWS * CC];   // LN'd q/k/v (A of proj GEMMs)
__device__ __half g_w[4][(size_t)CC * CC];      // Wq,Wk,Wv,Wo
__device__ __half g_p[3][(size_t)MROWS * CC];   // projected q/k/v
__device__ __half g_ao[(size_t)MROWS * CC];     // attention output (A of out GEMM)

// ---------------- helpers ----------------
__device__ __forceinline__ uint32_t s2u(const void* p) {
    uint32_t a;
    asm("{ .reg .u64 t; cvta.to.shared.u64 t, %1; cvt.u32.u64 %0, t; }" : "=r"(a) : "l"(p));
    return a;
}

__device__ __forceinline__ void cp16(uint32_t dst, const void* src) {
    asm volatile("cp.async.cg.shared.global [%0], [%1], 16;" :: "r"(dst), "l"(src) : "memory");
}

__device__ __forceinline__ void ldm4(uint32_t* r, uint32_t addr) {
    asm volatile("ldmatrix.sync.aligned.m8n8.x4.shared.b16 {%0,%1,%2,%3}, [%4];"
                 : "=r"(r[0]), "=r"(r[1]), "=r"(r[2]), "=r"(r[3]) : "r"(addr));
}

__device__ __forceinline__ void ldm4t(uint32_t* r, uint32_t addr) {
    asm volatile("ldmatrix.sync.aligned.m8n8.x4.trans.shared.b16 {%0,%1,%2,%3}, [%4];"
                 : "=r"(r[0]), "=r"(r[1]), "=r"(r[2]), "=r"(r[3]) : "r"(addr));
}

__device__ __forceinline__ void mma16816(float* c, const uint32_t* a, const uint32_t* b) {
    asm volatile(
        "mma.sync.aligned.m16n8k16.row.col.f32.f16.f16.f32 "
        "{%0,%1,%2,%3}, {%4,%5,%6,%7}, {%8,%9}, {%0,%1,%2,%3};"
        : "+f"(c[0]), "+f"(c[1]), "+f"(c[2]), "+f"(c[3])
        : "r"(a[0]), "r"(a[1]), "r"(a[2]), "r"(a[3]), "r"(b[0]), "r"(b[1]));
}

__device__ __forceinline__ uint32_t packh2(float a, float b) {
    __half2 h = __floats2half2_rn(a, b);
    return *reinterpret_cast<uint32_t*>(&h);
}

// ---------------- kernel 1: fused LayerNorm + fp16 convert, warp-per-row ----------------
__global__ __launch_bounds__(256) void split_ln_kernel(
    const float* __restrict__ q, const float* __restrict__ k, const float* __restrict__ v,
    const float* __restrict__ gq, const float* __restrict__ bq,
    const float* __restrict__ gk, const float* __restrict__ bk,
    const float* __restrict__ gv, const float* __restrict__ bv)
{
    const int lane = threadIdx.x & 31;
    const int row = blockIdx.x * 8 + (threadIdx.x >> 5);
    const int t = (row >= 2 * MROWS) ? 2 : (row >= MROWS ? 1 : 0);
    const int r = row - t * MROWS;
    const float* X = (t == 0 ? q : (t == 1 ? k : v)) + (size_t)r * CC;
    const float* G = (t == 0 ? gq : (t == 1 ? gk : gv));
    const float* Bb = (t == 0 ? bq : (t == 1 ? bk : bv));
    __half* H = g_a[t] + (size_t)r * CC;

    float4 u[4];
    float s = 0.f, ss = 0.f;
#pragma unroll
    for (int i = 0; i < 4; i++) {
        u[i] = reinterpret_cast<const float4*>(X)[lane + 32 * i];
        s  += u[i].x + u[i].y + u[i].z + u[i].w;
        ss += u[i].x * u[i].x + u[i].y * u[i].y + u[i].z * u[i].z + u[i].w * u[i].w;
    }
#pragma unroll
    for (int o = 16; o; o >>= 1) {
        s  += __shfl_xor_sync(0xffffffffu, s, o);
        ss += __shfl_xor_sync(0xffffffffu, ss, o);
    }
    float mu = s * (1.f / CC);
    float rs = rsqrtf(ss * (1.f / CC) - mu * mu + LN_EPS);

#pragma unroll
    for (int i = 0; i < 4; i++) {
        int j = lane + 32 * i;
        float4 g4 = reinterpret_cast<const float4*>(G)[j];
        float4 b4 = reinterpret_cast<const float4*>(Bb)[j];
        float y0 = (u[i].x - mu) * rs * g4.x + b4.x;
        float y1 = (u[i].y - mu) * rs * g4.y + b4.y;
        float y2 = (u[i].z - mu) * rs * g4.z + b4.z;
        float y3 = (u[i].w - mu) * rs * g4.w + b4.w;
        reinterpret_cast<uint2*>(H)[j] = make_uint2(packh2(y0, y1), packh2(y2, y3));
    }
}

// ---------------- kernel 2: weight fp32 -> fp16 (all 4 in one launch) ----------------
__global__ __launch_bounds__(256) void split_w_kernel(
    const float* __restrict__ w0, const float* __restrict__ w1,
    const float* __restrict__ w2, const float* __restrict__ w3)
{
    const int mode = blockIdx.y;
    const float* src = (mode == 0 ? w0 : (mode == 1 ? w1 : (mode == 2 ? w2 : w3)));
    __half* H = g_w[mode];
    int i = blockIdx.x * 256 + threadIdx.x;
    float4 u = reinterpret_cast<const float4*>(src)[i];
    reinterpret_cast<uint2*>(H)[i] = make_uint2(packh2(u.x, u.y), packh2(u.z, u.w));
}

// ---------------- kernel 3: HMMA fp16 GEMM (BK=32, 3-stage, 1 barrier/iter; R15 form) ----------------
#define TILE_B 8192
#define STAGE_B 16384
#define GSMEM (3 * STAGE_B)
#define NKI (CC / 32)

__global__ __launch_bounds__(256, 2)
void mma_gemm_kernel(int base_mode, float* __restrict__ out_param, const float* __restrict__ bias_param)
{
    extern __shared__ char smc[];
    const uint32_t sb = s2u(smc);
    const int tid = threadIdx.x, wid = tid >> 5, lane = tid & 31;
    const int warp_m = wid >> 2, warp_n = wid & 3;       // 2 x 4 warps
    const int m0 = blockIdx.y * 128, n0 = blockIdx.x * 128;
    const int mode = base_mode + blockIdx.z;

    const __half* A = (mode < 3) ? g_a[mode] : g_ao;
    const __half* B = g_w[mode];

    float acc[4][4][4];
#pragma unroll
    for (int i = 0; i < 4; i++)
#pragma unroll
        for (int j = 0; j < 4; j++)
#pragma unroll
            for (int x = 0; x < 4; x++) acc[i][j][x] = 0.f;

    const int lrow = tid >> 1;
    const int lc0  = (tid & 1) * 2;

    auto issue_loads = [&](int s, int k0) {
        uint32_t sst = sb + s * STAGE_B;
        const size_t ga = (size_t)(m0 + lrow) * CC + k0;
        const size_t gb = (size_t)(n0 + lrow) * CC + k0;
#pragma unroll
        for (int i = 0; i < 2; i++) {
            int c = lc0 + i;
            uint32_t d = (uint32_t)(lrow * 64 + ((c ^ ((lrow >> 1) & 3)) * 16));
            cp16(sst + 0 * TILE_B + d, A + ga + c * 8);
            cp16(sst + 1 * TILE_B + d, B + gb + c * 8);
        }
    };

    issue_loads(0, 0);
    asm volatile("cp.async.commit_group;" ::: "memory");
    issue_loads(1, 32);
    asm volatile("cp.async.commit_group;" ::: "memory");

    for (int it = 0; it < NKI; it++) {
        asm volatile("cp.async.wait_group 1;" ::: "memory");
        __syncthreads();   // all warps done reading the buffer we are about to refill

        if (it + 2 < NKI) issue_loads((it + 2) % 3, (it + 2) * 32);
        asm volatile("cp.async.commit_group;" ::: "memory");

        const uint32_t st = sb + (it % 3) * STAGE_B;
#pragma unroll
        for (int kk = 0; kk < 2; kk++) {
            uint32_t af[4][4], bf[2][4];
            int ar = warp_m * 64 + (lane & 7) + ((lane >> 3) & 1) * 8;
            int ac = kk * 2 + ((lane >> 4) & 1);
            int br = warp_n * 32 + (lane & 7) + ((lane >> 4) & 1) * 8;
            int bc = kk * 2 + ((lane >> 3) & 1);

#pragma unroll
            for (int np = 0; np < 2; np++) {
                int r = br + np * 16;
                ldm4(bf[np], st + 1 * TILE_B + r * 64 + ((bc ^ ((r >> 1) & 3)) * 16));
            }
#pragma unroll
            for (int mt = 0; mt < 4; mt++) {
                int r = ar + mt * 16;
                ldm4(af[mt], st + 0 * TILE_B + r * 64 + ((ac ^ ((r >> 1) & 3)) * 16));
            }
#pragma unroll
            for (int mt = 0; mt < 4; mt++)
#pragma unroll
                for (int nt = 0; nt < 4; nt++)
                    mma16816(acc[mt][nt], af[mt], &bf[nt >> 1][(nt & 1) * 2]);
        }
    }

    if (mode < 3) {
        __half* H = g_p[mode];
#pragma unroll
        for (int mt = 0; mt < 4; mt++) {
#pragma unroll
            for (int nt = 0; nt < 4; nt++) {
                int r = m0 + warp_m * 64 + mt * 16 + (lane >> 2);
                int col = n0 + warp_n * 32 + nt * 8 + (lane & 3) * 2;
                *reinterpret_cast<uint32_t*>(H + (size_t)r * CC + col) =
                    packh2(acc[mt][nt][0], acc[mt][nt][1]);
                *reinterpret_cast<uint32_t*>(H + (size_t)(r + 8) * CC + col) =
                    packh2(acc[mt][nt][2], acc[mt][nt][3]);
            }
        }
    } else {
        float* O = out_param;
        const float* bias = bias_param;
#pragma unroll
        for (int mt = 0; mt < 4; mt++) {
#pragma unroll
            for (int nt = 0; nt < 4; nt++) {
                int r = m0 + warp_m * 64 + mt * 16 + (lane >> 2);
                int col = n0 + warp_n * 32 + nt * 8 + (lane & 3) * 2;
                float b0 = bias[col], b1 = bias[col + 1];
                float2 v0 = {acc[mt][nt][0] + b0, acc[mt][nt][1] + b1};
                float2 v1 = {acc[mt][nt][2] + b0, acc[mt][nt][3] + b1};
                *reinterpret_cast<float2*>(O + (size_t)r * CC + col) = v0;
                *reinterpret_cast<float2*>(O + (size_t)(r + 8) * CC + col) = v1;
            }
        }
    }
}

// ---------------- kernel 4: fp16 attention, 512 thr / 16 warps, no-max softmax ----------------
#define AK 0
#define AV 32768
#define AQ 65536
#define STT 73728
#define AOPH 75776
#define ASMEM (AOPH + 32768)   // 108544

// fp16 partial-O word address: buffer wb, row wr (0..63), logical col-word lw (0..31)
__device__ __forceinline__ uint32_t opw(int wb, int wr, int lw) {
    return (uint32_t)(AOPH + wb * 8192 + wr * 128 + ((lw ^ ((wr & 7) << 2)) << 2));
}

__global__ __launch_bounds__(512, 1) void attn_tc_kernel(
    const float* __restrict__ mask, const float* __restrict__ pos)
{
    extern __shared__ char smc[];
    const uint32_t sb = s2u(smc);
    const int h = blockIdx.x, bp = blockIdx.y;
    const int tid = threadIdx.x, wid = tid >> 5, lane = tid & 31;
    const int warp_m = wid >> 2, warp_n = wid & 3;    // 4 x 4 warps
    const int g = lane >> 2, tg = lane & 3;

    // K/V tiles: 256 rows x 64 fp16 = 128B rows, SW swizzle on 8 chunks
    for (int i = tid; i < 2048; i += 512) {
        int row = i >> 3, c = i & 7;
        uint32_t d = (uint32_t)(row * 128 + ((c ^ (row & 7)) << 4));
        size_t gg = (size_t)(bp * NN + row) * CC + h * DD + c * 8;
        cp16(sb + AK + d, g_p[1] + gg);
        cp16(sb + AV + d, g_p[2] + gg);
    }
    asm volatile("cp.async.commit_group;" ::: "memory");

    const size_t mbase = (size_t)bp * NN * NN;
    const size_t pbase = (size_t)h * NN * NN;

    for (int it = 0; it < 4; it++) {
        // Q tile (64 rows x 8 chunks = 512), one chunk per thread
        {
            int row = tid >> 3, c = tid & 7;
            uint32_t d = (uint32_t)(row * 128 + ((c ^ (row & 7)) << 4));
            size_t gg = (size_t)(bp * NN + it * 64 + row) * CC + h * DD + c * 8;
            cp16(sb + AQ + d, g_p[0] + gg);
        }
        asm volatile("cp.async.commit_group;" ::: "memory");
        asm volatile("cp.async.wait_group 0;" ::: "memory");
        __syncthreads();

        // ---- S = Q K^T (warp: 16 rows x 64 cols, k=64), kept in regs ----
        float cS[8][4];
#pragma unroll
        for (int i = 0; i < 8; i++)
#pragma unroll
            for (int x = 0; x < 4; x++) cS[i][x] = 0.f;

#pragma unroll
        for (int ks = 0; ks < 4; ks++) {
            uint32_t ah[4];
            {
                int ar = warp_m * 16 + (lane & 7) + ((lane >> 3) & 1) * 8;
                int ac = ks * 2 + ((lane >> 4) & 1);
                ldm4(ah, sb + AQ + ar * 128 + (((ac ^ (ar & 7)) & 7) << 4));
            }
#pragma unroll
            for (int nt2 = 0; nt2 < 4; nt2++) {
                int br = warp_n * 64 + nt2 * 16 + (lane & 7) + ((lane >> 4) & 1) * 8;
                int bc = ks * 2 + ((lane >> 3) & 1);
                uint32_t bh[4];
                ldm4(bh, sb + AK + br * 128 + (((bc ^ (br & 7)) & 7) << 4));
                mma16816(cS[2 * nt2],     ah, bh);
                mma16816(cS[2 * nt2 + 1], ah, bh + 2);
            }
        }

        // ---- e = exp(mask*(s*INV_TEMP + pos)) in regs (no max subtraction) ----
        float s0 = 0.f, s1 = 0.f;
        {
            const int i0 = warp_m * 16 + g;
            const size_t mr0 = mbase + (size_t)(it * 64 + i0) * NN;
            const size_t pr0 = pbase + (size_t)(it * 64 + i0) * NN;
#pragma unroll
            for (int nt = 0; nt < 8; nt++) {
                int j = warp_n * 64 + nt * 8 + 2 * tg;
                float2 m0 = __ldg(reinterpret_cast<const float2*>(mask + mr0 + j));
                float2 p0 = __ldg(reinterpret_cast<const float2*>(pos  + pr0 + j));
                float2 m1 = __ldg(reinterpret_cast<const float2*>(mask + mr0 + 8 * NN + j));
                float2 p1 = __ldg(reinterpret_cast<const float2*>(pos  + pr0 + 8 * NN + j));
                cS[nt][0] = __expf(m0.x * (cS[nt][0] * INV_TEMP + p0.x));
                cS[nt][1] = __expf(m0.y * (cS[nt][1] * INV_TEMP + p0.y));
                cS[nt][2] = __expf(m1.x * (cS[nt][2] * INV_TEMP + p1.x));
                cS[nt][3] = __expf(m1.y * (cS[nt][3] * INV_TEMP + p1.y));
                s0 += cS[nt][0] + cS[nt][1];
                s1 += cS[nt][2] + cS[nt][3];
            }
        }
#pragma unroll
        for (int o = 1; o <= 2; o <<= 1) {
            s0 += __shfl_xor_sync(0xffffffffu, s0, o);
            s1 += __shfl_xor_sync(0xffffffffu, s1, o);
        }
        if (tg == 0) {
            int r0 = warp_m * 16 + g;
            *reinterpret_cast<float*>(smc + STT + (r0 * 4 + warp_n) * 4)       = s0;
            *reinterpret_cast<float*>(smc + STT + ((r0 + 8) * 4 + warp_n) * 4) = s1;
        }
        __syncthreads();

        // ---- global scale per row: 1 / total ----
        float sc0, sc1;
        {
            int r0 = warp_m * 16 + g;
            float4 a0 = *reinterpret_cast<float4*>(smc + STT + r0 * 16);
            sc0 = 1.f / (a0.x + a0.y + a0.z + a0.w);
            float4 b0 = *reinterpret_cast<float4*>(smc + STT + (r0 + 8) * 16);
            sc1 = 1.f / (b0.x + b0.y + b0.z + b0.w);
        }

        // ---- build P A-fragments from registers (FA2 C->A identity) ----
        uint32_t af[4][4];
#pragma unroll
        for (int kk = 0; kk < 4; kk++) {
            af[kk][0] = packh2(cS[2 * kk][0] * sc0,     cS[2 * kk][1] * sc0);
            af[kk][1] = packh2(cS[2 * kk][2] * sc1,     cS[2 * kk][3] * sc1);
            af[kk][2] = packh2(cS[2 * kk + 1][0] * sc0, cS[2 * kk + 1][1] * sc0);
            af[kk][3] = packh2(cS[2 * kk + 1][2] * sc1, cS[2 * kk + 1][3] * sc1);
        }

        // ---- partial O = P_slice @ V_slice (warp: 16 rows x 64 d-cols, k=64) ----
        float o[8][4];
#pragma unroll
        for (int i = 0; i < 8; i++)
#pragma unroll
            for (int x = 0; x < 4; x++) o[i][x] = 0.f;

#pragma unroll
        for (int ks = 0; ks < 4; ks++) {
#pragma unroll
            for (int nt16 = 0; nt16 < 4; nt16++) {
                int vr = warp_n * 64 + ks * 16 + (lane & 7) + ((lane >> 3) & 1) * 8;
                int vc = nt16 * 2 + ((lane >> 4) & 1);
                uint32_t bh[4];
                ldm4t(bh, sb + AV + vr * 128 + (((vc ^ (vr & 7)) & 7) << 4));
                mma16816(o[nt16 * 2],     af[ks], bh);
                mma16816(o[nt16 * 2 + 1], af[ks], bh + 2);
            }
        }

        // ---- write partial O (packed fp16) to this warp's buffer ----
        {
            int wr = warp_m * 16 + g;
#pragma unroll
            for (int nt = 0; nt < 8; nt++) {
                int lw = nt * 4 + tg;
                *reinterpret_cast<uint32_t*>(smc + opw(warp_n, wr, lw))     = packh2(o[nt][0], o[nt][1]);
                *reinterpret_cast<uint32_t*>(smc + opw(warp_n, wr + 8, lw)) = packh2(o[nt][2], o[nt][3]);
            }
        }
        __syncthreads();

        // ---- final: sum 4 fp16 partials, write fp16 g_ao ----
        {
            int ro = tid >> 3, jg = tid & 7;
            uint32_t base = (uint32_t)(AOPH + ro * 128 + ((uint32_t)(jg ^ (ro & 7)) << 4));
            float acc8[8];
#pragma unroll
            for (int x = 0; x < 8; x++) acc8[x] = 0.f;
#pragma unroll
            for (int w = 0; w < 4; w++) {
                uint4 u = *reinterpret_cast<uint4*>(smc + base + w * 8192);
                __half2 h0 = *reinterpret_cast<__half2*>(&u.x);
                __half2 h1 = *reinterpret_cast<__half2*>(&u.y);
                __half2 h2 = *reinterpret_cast<__half2*>(&u.z);
                __half2 h3 = *reinterpret_cast<__half2*>(&u.w);
                acc8[0] += __low2float(h0); acc8[1] += __high2float(h0);
                acc8[2] += __low2float(h1); acc8[3] += __high2float(h1);
                acc8[4] += __low2float(h2); acc8[5] += __high2float(h2);
                acc8[6] += __low2float(h3); acc8[7] += __high2float(h3);
            }
            uint4 wv;
            wv.x = packh2(acc8[0], acc8[1]);
            wv.y = packh2(acc8[2], acc8[3]);
            wv.z = packh2(acc8[4], acc8[5]);
            wv.w = packh2(acc8[6], acc8[7]);
            size_t gg = (size_t)(bp * NN + it * 64 + ro) * CC + h * DD + jg * 8;
            *reinterpret_cast<uint4*>(g_ao + gg) = wv;
        }
        // no barrier needed: next iter's smem writes are all behind its own barriers
    }
}

// ---------------- launch ----------------
extern "C" void kernel_launch(void* const* d_in, const int* in_sizes, int n_in,
                              void* d_out, int out_size)
{
    const float* q    = (const float*)d_in[0];
    const float* k    = (const float*)d_in[1];
    const float* v    = (const float*)d_in[2];
    const float* mask = (const float*)d_in[3];
    const float* pos  = (const float*)d_in[4];
    const float* gq   = (const float*)d_in[5];
    const float* bq   = (const float*)d_in[6];
    const float* gk   = (const float*)d_in[7];
    const float* bk   = (const float*)d_in[8];
    const float* gv   = (const float*)d_in[9];
    const float* bv   = (const float*)d_in[10];
    const float* Wq   = (const float*)d_in[11];
    const float* Wk   = (const float*)d_in[12];
    const float* Wv   = (const float*)d_in[13];
    const float* Wo   = (const float*)d_in[14];
    const float* bo   = (const float*)d_in[15];
    float* out = (float*)d_out;

    static bool attr_done = false;
    if (!attr_done) {
        cudaFuncSetAttribute(attn_tc_kernel, cudaFuncAttributeMaxDynamicSharedMemorySize, ASMEM);
        cudaFuncSetAttribute(mma_gemm_kernel, cudaFuncAttributeMaxDynamicSharedMemorySize, GSMEM);
        attr_done = true;
    }

    // 1. LN + fp16 convert of q,k,v (warp per row)
    split_ln_kernel<<<3 * MROWS / 8, 256>>>(q, k, v, gq, bq, gk, bk, gv, bv);

    // 2. weights -> fp16 (one launch, 4 modes)
    split_w_kernel<<<dim3(CC * CC / 4 / 256, 4), 256>>>(Wq, Wk, Wv, Wo);

    // 3. projection GEMMs (modes 0..2 via blockIdx.z)
    dim3 gp(CC / 128, MROWS / 128, 3);
    mma_gemm_kernel<<<gp, 256, GSMEM>>>(0, nullptr, nullptr);

    // 4. fp16 attention, register-resident P, no-max softmax
    attn_tc_kernel<<<dim3(HH, BP), 512, ASMEM>>>(mask, pos);

    // 5. output GEMM + bias
    dim3 go(CC / 128, MROWS / 128, 1);
    mma_gemm_kernel<<<go, 256, GSMEM>>>(3, out, bo);
}